// round 1
// baseline (speedup 1.0000x reference)
#include <cuda_runtime.h>
#include <cuda_bf16.h>
#include <cstdint>

// HyperedgeMaxAggregator: out[s, f] = max over members i with segment_ids[i]==s
// of features[node_ids[i], f].  segment_ids sorted. F = 64.
//
// Plan:
//  K1 (init): fill d_out with -inf, and detect whether the id arrays are
//             int64 or int32 (JAX without x64 silently downcasts) by checking
//             odd 32-bit words of node_ids.
//  K2 (main): one warp per contiguous chunk of CHUNK members. 32 lanes x
//             float2 running max (one coalesced 256B row per member).
//             Interior segments -> plain float2 store (exclusive ownership).
//             First/last segment of each chunk -> float atomic-max
//             (int atomicMax for >=0, uint atomicMin for <0) against the
//             -inf-initialized output.

#define FEAT 64
#define CHUNK 128          // members per warp
#define WPB 8              // warps per block (256 threads)

__device__ int g_ids_are_64 = 0;

static __device__ __forceinline__ float neg_inf_f() {
    return __int_as_float(0xff800000);
}

static __device__ __forceinline__ void atomic_max_float(float* addr, float v) {
    if (v >= 0.0f) {
        atomicMax((int*)addr, __float_as_int(v));
    } else {
        atomicMin((unsigned int*)addr, __float_as_uint(v));
    }
}

__global__ void init_kernel(float* __restrict__ out, int out_size,
                            const int* __restrict__ node_ids_as_i32) {
    int tid = blockIdx.x * blockDim.x + threadIdx.x;
    if (tid == 0) {
        // If ids are little-endian int64 with values < 2^31, every odd 32-bit
        // word is 0. For int32 data these words are uniform random node ids;
        // P(8 consecutive odd words all zero) ~ 1e-40.
        bool all_zero = true;
#pragma unroll
        for (int k = 1; k <= 15; k += 2) {
            all_zero = all_zero && (node_ids_as_i32[k] == 0);
        }
        g_ids_are_64 = all_zero ? 1 : 0;
    }
    const float ni = neg_inf_f();
    float4 v4 = make_float4(ni, ni, ni, ni);
    int n4 = out_size >> 2;                 // out_size is a multiple of 64
    float4* out4 = (float4*)out;
    for (int i = tid; i < n4; i += gridDim.x * blockDim.x) {
        out4[i] = v4;
    }
}

template <bool IS64>
static __device__ __forceinline__ int get_id(const void* __restrict__ p, int i) {
    if (IS64) {
        return (int)__ldg(&((const long long*)p)[i]);
    } else {
        return __ldg(&((const int*)p)[i]);
    }
}

static __device__ __forceinline__ void flush_seg(float* __restrict__ out,
                                                 int sid, int lane,
                                                 float2 m, bool use_atomic) {
    float* p = out + (size_t)sid * FEAT + lane * 2;
    if (use_atomic) {
        atomic_max_float(p,     m.x);
        atomic_max_float(p + 1, m.y);
    } else {
        *(float2*)p = m;   // 8B-aligned: sid*256B + lane*8B
    }
}

template <bool IS64>
static __device__ __forceinline__ void seg_body(
    const float2* __restrict__ feat2,       // features viewed as [N, 32] float2
    const void* __restrict__ node_ids,
    const void* __restrict__ seg_ids,
    float* __restrict__ out,
    int n_members)
{
    int gwarp = (blockIdx.x * blockDim.x + threadIdx.x) >> 5;
    int lane  = threadIdx.x & 31;
    int start = gwarp * CHUNK;
    if (start >= n_members) return;
    int end = min(start + CHUNK, n_members);

    const float ni = neg_inf_f();
    int   cur = get_id<IS64>(seg_ids, start);
    float2 m  = make_float2(ni, ni);
    bool first_seg = true;   // first segment may extend into previous chunk

#pragma unroll 4
    for (int i = start; i < end; ++i) {
        int s = get_id<IS64>(seg_ids, i);
        if (s != cur) {
            // cur started inside this chunk iff !first_seg, and it ends here
            // (we observed the transition) -> interior => plain store.
            flush_seg(out, cur, lane, m, first_seg);
            first_seg = false;
            cur = s;
            m = make_float2(ni, ni);
        }
        int nid = get_id<IS64>(node_ids, i);
        float2 v = __ldg(&feat2[(size_t)nid * (FEAT / 2) + lane]);
        m.x = fmaxf(m.x, v.x);
        m.y = fmaxf(m.y, v.y);
    }
    // Last segment may extend into the next chunk -> atomic.
    flush_seg(out, cur, lane, m, true);
}

__global__ void __launch_bounds__(WPB * 32)
seg_max_kernel(const float* __restrict__ features,
               const void* __restrict__ node_ids,
               const void* __restrict__ seg_ids,
               float* __restrict__ out,
               int n_members)
{
    const float2* feat2 = (const float2*)features;
    if (g_ids_are_64) {
        seg_body<true>(feat2, node_ids, seg_ids, out, n_members);
    } else {
        seg_body<false>(feat2, node_ids, seg_ids, out, n_members);
    }
}

extern "C" void kernel_launch(void* const* d_in, const int* in_sizes, int n_in,
                              void* d_out, int out_size) {
    const float* features = (const float*)d_in[0];
    const void*  node_ids = d_in[1];
    const void*  seg_ids  = d_in[2];
    float*       out      = (float*)d_out;

    int n_members = in_sizes[1];

    // K1: -inf init + id-width detection.
    {
        int n4 = out_size >> 2;
        int threads = 256;
        int blocks = (n4 + threads - 1) / threads;
        if (blocks > 1024) blocks = 1024;
        if (blocks < 1) blocks = 1;
        init_kernel<<<blocks, threads>>>(out, out_size, (const int*)node_ids);
    }

    // K2: segment max.
    if (n_members > 0) {
        int warps  = (n_members + CHUNK - 1) / CHUNK;
        int blocks = (warps + WPB - 1) / WPB;
        seg_max_kernel<<<blocks, WPB * 32>>>(features, node_ids, seg_ids, out,
                                             n_members);
    }
}

// round 2
// speedup vs baseline: 1.3265x; 1.3265x over previous
#include <cuda_runtime.h>
#include <cuda_bf16.h>
#include <cstdint>

// HyperedgeMaxAggregator: out[s, f] = max over members i with segment_ids[i]==s
// of features[node_ids[i], f].  segment_ids sorted. F = 64.
//
// R2: register-resident id stream. Each lane loads ids[base+lane] (coalesced),
// broadcasts via shfl. 32-member batches, feature loads prefetched in groups
// of 8 -> MLP ~8 per warp (R1 was serial, issue=35%, latency-bound at 48us).

#define FEAT 64
#define CHUNK 128          // members per warp
#define WPB 8              // warps per block (256 threads)
#define PF 8               // prefetch group

__device__ int g_ids_are_64 = 0;

static __device__ __forceinline__ float neg_inf_f() {
    return __int_as_float(0xff800000);
}

static __device__ __forceinline__ void atomic_max_float(float* addr, float v) {
    if (v >= 0.0f) {
        atomicMax((int*)addr, __float_as_int(v));
    } else {
        atomicMin((unsigned int*)addr, __float_as_uint(v));
    }
}

__global__ void init_kernel(float* __restrict__ out, int out_size,
                            const int* __restrict__ node_ids_as_i32) {
    int tid = blockIdx.x * blockDim.x + threadIdx.x;
    if (tid == 0) {
        // int64 ids (values < 2^31, little-endian) have all odd 32-bit words 0.
        bool all_zero = true;
#pragma unroll
        for (int k = 1; k <= 15; k += 2) {
            all_zero = all_zero && (node_ids_as_i32[k] == 0);
        }
        g_ids_are_64 = all_zero ? 1 : 0;
    }
    const float ni = neg_inf_f();
    float4 v4 = make_float4(ni, ni, ni, ni);
    int n4 = out_size >> 2;
    float4* out4 = (float4*)out;
    for (int i = tid; i < n4; i += gridDim.x * blockDim.x) {
        out4[i] = v4;
    }
}

template <bool IS64>
static __device__ __forceinline__ int get_id(const void* __restrict__ p, int i) {
    if (IS64) {
        return (int)__ldg(&((const long long*)p)[i]);
    } else {
        return __ldg(&((const int*)p)[i]);
    }
}

static __device__ __forceinline__ void flush_seg(float* __restrict__ out,
                                                 int sid, int lane,
                                                 float2 m, bool use_atomic) {
    float* p = out + (size_t)sid * FEAT + lane * 2;
    if (use_atomic) {
        atomic_max_float(p,     m.x);
        atomic_max_float(p + 1, m.y);
    } else {
        *(float2*)p = m;
    }
}

template <bool IS64>
static __device__ __forceinline__ void seg_body(
    const float2* __restrict__ feat2,       // features as [N, 32] float2
    const void* __restrict__ node_ids,
    const void* __restrict__ seg_ids,
    float* __restrict__ out,
    int n_members)
{
    int gwarp = (blockIdx.x * blockDim.x + threadIdx.x) >> 5;
    int lane  = threadIdx.x & 31;
    int start = gwarp * CHUNK;
    if (start >= n_members) return;
    int end = min(start + CHUNK, n_members);

    const float ni = neg_inf_f();
    int    cur = get_id<IS64>(seg_ids, start);
    float2 m   = make_float2(ni, ni);
    bool first_seg = true;   // first segment may extend into the previous chunk

    int base = start;
    // ---- fast path: full 32-member batches ----
    for (; base + 32 <= end; base += 32) {
        // one coalesced load per lane instead of 64 broadcast loads
        int my_nid = get_id<IS64>(node_ids, base + lane);
        int my_sid = get_id<IS64>(seg_ids,  base + lane);

#pragma unroll
        for (int j = 0; j < 32; j += PF) {
            float2 v[PF];
            // issue PF independent feature loads up front (MLP = PF)
#pragma unroll
            for (int k = 0; k < PF; ++k) {
                int nid = __shfl_sync(0xffffffffu, my_nid, j + k);
                v[k] = __ldg(&feat2[(size_t)nid * (FEAT / 2) + lane]);
            }
#pragma unroll
            for (int k = 0; k < PF; ++k) {
                int s = __shfl_sync(0xffffffffu, my_sid, j + k);
                if (s != cur) {
                    flush_seg(out, cur, lane, m, first_seg);
                    first_seg = false;
                    cur = s;
                    m = make_float2(ni, ni);
                }
                m.x = fmaxf(m.x, v[k].x);
                m.y = fmaxf(m.y, v[k].y);
            }
        }
    }
    // ---- tail: serial ----
    for (int i = base; i < end; ++i) {
        int s = get_id<IS64>(seg_ids, i);
        if (s != cur) {
            flush_seg(out, cur, lane, m, first_seg);
            first_seg = false;
            cur = s;
            m = make_float2(ni, ni);
        }
        int nid = get_id<IS64>(node_ids, i);
        float2 v = __ldg(&feat2[(size_t)nid * (FEAT / 2) + lane]);
        m.x = fmaxf(m.x, v.x);
        m.y = fmaxf(m.y, v.y);
    }
    // last segment may extend into the next chunk -> atomic
    flush_seg(out, cur, lane, m, true);
}

__global__ void __launch_bounds__(WPB * 32)
seg_max_kernel(const float* __restrict__ features,
               const void* __restrict__ node_ids,
               const void* __restrict__ seg_ids,
               float* __restrict__ out,
               int n_members)
{
    const float2* feat2 = (const float2*)features;
    if (g_ids_are_64) {
        seg_body<true>(feat2, node_ids, seg_ids, out, n_members);
    } else {
        seg_body<false>(feat2, node_ids, seg_ids, out, n_members);
    }
}

extern "C" void kernel_launch(void* const* d_in, const int* in_sizes, int n_in,
                              void* d_out, int out_size) {
    const float* features = (const float*)d_in[0];
    const void*  node_ids = d_in[1];
    const void*  seg_ids  = d_in[2];
    float*       out      = (float*)d_out;

    int n_members = in_sizes[1];

    {
        int n4 = out_size >> 2;
        int threads = 256;
        int blocks = (n4 + threads - 1) / threads;
        if (blocks > 1024) blocks = 1024;
        if (blocks < 1) blocks = 1;
        init_kernel<<<blocks, threads>>>(out, out_size, (const int*)node_ids);
    }

    if (n_members > 0) {
        int warps  = (n_members + CHUNK - 1) / CHUNK;
        int blocks = (warps + WPB - 1) / WPB;
        seg_max_kernel<<<blocks, WPB * 32>>>(features, node_ids, seg_ids, out,
                                             n_members);
    }
}

// round 3
// speedup vs baseline: 1.6505x; 1.2443x over previous
#include <cuda_runtime.h>
#include <cuda_bf16.h>
#include <cstdint>

// HyperedgeMaxAggregator: out[s, f] = max over members i with segment_ids[i]==s
// of features[node_ids[i], f].  segment_ids sorted. F = 64.
//
// R3: ballot-based transition mask (no per-member sid shfl / compare),
// 32-bit address math, launch_bounds for occupancy, CHUNK=64 for balance.

#define FEAT 64
#define CHUNK 64           // members per warp
#define WPB 8              // warps per block (256 threads)
#define PF 8               // prefetch group (MLP)

__device__ int g_ids_are_64 = 0;

static __device__ __forceinline__ float neg_inf_f() {
    return __int_as_float(0xff800000);
}

static __device__ __forceinline__ void atomic_max_float(float* addr, float v) {
    if (v >= 0.0f) {
        atomicMax((int*)addr, __float_as_int(v));
    } else {
        atomicMin((unsigned int*)addr, __float_as_uint(v));
    }
}

__global__ void init_kernel(float* __restrict__ out, int out_size,
                            const int* __restrict__ node_ids_as_i32) {
    int tid = blockIdx.x * blockDim.x + threadIdx.x;
    if (tid == 0) {
        // int64 ids (values < 2^31, little-endian) have all odd 32-bit words 0.
        bool all_zero = true;
#pragma unroll
        for (int k = 1; k <= 15; k += 2) {
            all_zero = all_zero && (node_ids_as_i32[k] == 0);
        }
        g_ids_are_64 = all_zero ? 1 : 0;
    }
    const float ni = neg_inf_f();
    float4 v4 = make_float4(ni, ni, ni, ni);
    int n4 = out_size >> 2;
    float4* out4 = (float4*)out;
    for (int i = tid; i < n4; i += gridDim.x * blockDim.x) {
        out4[i] = v4;
    }
}

template <bool IS64>
static __device__ __forceinline__ int get_id(const void* __restrict__ p, int i) {
    if (IS64) {
        return (int)__ldg(&((const long long*)p)[i]);
    } else {
        return __ldg(&((const int*)p)[i]);
    }
}

static __device__ __forceinline__ void flush_seg(float* __restrict__ out,
                                                 int sid, int lane,
                                                 float2 m, bool use_atomic) {
    // 32-bit offset: sid*64 + lane*2 floats (out <= 12.8 MB)
    float* p = out + (((uint32_t)sid << 6) + (uint32_t)(lane << 1));
    if (use_atomic) {
        atomic_max_float(p,     m.x);
        atomic_max_float(p + 1, m.y);
    } else {
        *(float2*)p = m;
    }
}

template <bool IS64>
static __device__ __forceinline__ void seg_body(
    const char* __restrict__ feat_bytes,    // features base
    const void* __restrict__ node_ids,
    const void* __restrict__ seg_ids,
    float* __restrict__ out,
    int n_members)
{
    int gwarp = (blockIdx.x * blockDim.x + threadIdx.x) >> 5;
    int lane  = threadIdx.x & 31;
    int start = gwarp * CHUNK;
    if (start >= n_members) return;
    int end = min(start + CHUNK, n_members);

    // per-lane adjusted base: row byte offset is nid << 8 (features <= 25.6 MB)
    const char* fbase = feat_bytes + (uint32_t)(lane << 3);

    const float ni = neg_inf_f();
    int    cur = get_id<IS64>(seg_ids, start);
    float2 m   = make_float2(ni, ni);
    bool first_seg = true;   // first segment may extend into previous chunk

    int base = start;
    // ---- fast path: full 32-member batches ----
    for (; base + 32 <= end; base += 32) {
        int my_nid = get_id<IS64>(node_ids, base + lane);
        int my_sid = get_id<IS64>(seg_ids,  base + lane);

        // transition bitmap: bit k set iff member base+k starts a new segment
        int up   = __shfl_up_sync(0xffffffffu, my_sid, 1);
        bool dif = (lane == 0) ? (my_sid != cur) : (my_sid != up);
        uint32_t tmask = __ballot_sync(0xffffffffu, dif);

#pragma unroll
        for (int j = 0; j < 32; j += PF) {
            float2 v[PF];
            // issue PF independent feature loads up front (MLP = PF)
#pragma unroll
            for (int k = 0; k < PF; ++k) {
                int nid = __shfl_sync(0xffffffffu, my_nid, j + k);
                v[k] = __ldg((const float2*)(fbase + ((uint32_t)nid << 8)));
            }
#pragma unroll
            for (int k = 0; k < PF; ++k) {
                if (tmask & (1u << (j + k))) {      // warp-uniform branch
                    flush_seg(out, cur, lane, m, first_seg);
                    first_seg = false;
                    cur = __shfl_sync(0xffffffffu, my_sid, j + k);
                    m = make_float2(ni, ni);
                }
                m.x = fmaxf(m.x, v[k].x);
                m.y = fmaxf(m.y, v[k].y);
            }
        }
    }
    // ---- tail: serial ----
    for (int i = base; i < end; ++i) {
        int s = get_id<IS64>(seg_ids, i);
        if (s != cur) {
            flush_seg(out, cur, lane, m, first_seg);
            first_seg = false;
            cur = s;
            m = make_float2(ni, ni);
        }
        int nid = get_id<IS64>(node_ids, i);
        float2 v = __ldg((const float2*)(fbase + ((uint32_t)nid << 8)));
        m.x = fmaxf(m.x, v.x);
        m.y = fmaxf(m.y, v.y);
    }
    // last segment may extend into the next chunk -> atomic
    flush_seg(out, cur, lane, m, true);
}

__global__ void __launch_bounds__(WPB * 32, 6)
seg_max_kernel(const float* __restrict__ features,
               const void* __restrict__ node_ids,
               const void* __restrict__ seg_ids,
               float* __restrict__ out,
               int n_members)
{
    const char* fb = (const char*)features;
    if (g_ids_are_64) {
        seg_body<true>(fb, node_ids, seg_ids, out, n_members);
    } else {
        seg_body<false>(fb, node_ids, seg_ids, out, n_members);
    }
}

extern "C" void kernel_launch(void* const* d_in, const int* in_sizes, int n_in,
                              void* d_out, int out_size) {
    const float* features = (const float*)d_in[0];
    const void*  node_ids = d_in[1];
    const void*  seg_ids  = d_in[2];
    float*       out      = (float*)d_out;

    int n_members = in_sizes[1];

    {
        int n4 = out_size >> 2;
        int threads = 256;
        int blocks = (n4 + threads - 1) / threads;
        if (blocks > 1024) blocks = 1024;
        if (blocks < 1) blocks = 1;
        init_kernel<<<blocks, threads>>>(out, out_size, (const int*)node_ids);
    }

    if (n_members > 0) {
        int warps  = (n_members + CHUNK - 1) / CHUNK;
        int blocks = (warps + WPB - 1) / WPB;
        seg_max_kernel<<<blocks, WPB * 32>>>(features, node_ids, seg_ids, out,
                                             n_members);
    }
}